// round 10
// baseline (speedup 1.0000x reference)
#include <cuda_runtime.h>
#include <cuda_bf16.h>
#include <cstdint>

#define HID   2048
#define NH    16
#define DH    128
#define HARM  64
#define BATCH 2
#define SEQ   2048
#define MTOT  (BATCH*SEQ)   // 4096

// ---------------- scratch (static device globals; no allocs allowed) --------
__device__ float g_w[4 * HID * HARM];          // amp*cos(phase) q,k,v,o
__device__ float g_bascat[3 * HARM * HID];     // concat basis q|k|v
__device__ float g_resq[MTOT * HARM];          // Res_q fp32 (for tproj)
__device__ float g_G[NH * HARM * HARM];        // Gt[(h,j)][k] = (Wq_h^T Wk_h)[k,j]
__device__ float g_C[HARM * NH * HARM];        // C[j][(h,i)] = (Bo_h Wv_h)[j,i]
__device__ __align__(256) __nv_bfloat16 g_th[MTOT * NH * HARM];  // T hi (b,h,s,64), K2-scaled
__device__ __align__(256) __nv_bfloat16 g_tl[MTOT * NH * HARM];
__device__ __align__(256) __nv_bfloat16 g_rkh[MTOT * HARM];      // Res_k hi (b,s,64)
__device__ __align__(256) __nv_bfloat16 g_rkl[MTOT * HARM];
__device__ __align__(256) __nv_bfloat16 g_rvh[MTOT * HARM];      // Res_v^T hi (b,64,s)
__device__ __align__(256) __nv_bfloat16 g_rvl[MTOT * HARM];
__device__ __align__(256) float g_u[MTOT * NH * HARM];           // U (b,s,h,64) fp32
__device__ float g_reso4[4 * MTOT * HARM];     // split-K partials of res_o

// ---------------- PTX helpers (portable: sm_80+ features only) ---------------
__device__ __forceinline__ uint32_t smem_u32(const void* p) {
    uint32_t a;
    asm("{ .reg .u64 t; cvta.to.shared.u64 t, %1; cvt.u32.u64 %0, t; }" : "=r"(a) : "l"(p));
    return a;
}
__device__ __forceinline__ void ldsm4(uint32_t r[4], uint32_t addr) {
    asm volatile("ldmatrix.sync.aligned.m8n8.x4.shared.b16 {%0,%1,%2,%3}, [%4];"
                 : "=r"(r[0]), "=r"(r[1]), "=r"(r[2]), "=r"(r[3]) : "r"(addr));
}
__device__ __forceinline__ void mma16816(float d[4], const uint32_t a[4],
                                         uint32_t b0, uint32_t b1) {
    asm volatile("mma.sync.aligned.m16n8k16.row.col.f32.bf16.bf16.f32 "
                 "{%0,%1,%2,%3}, {%4,%5,%6,%7}, {%8,%9}, {%0,%1,%2,%3};"
                 : "+f"(d[0]), "+f"(d[1]), "+f"(d[2]), "+f"(d[3])
                 : "r"(a[0]), "r"(a[1]), "r"(a[2]), "r"(a[3]), "r"(b0), "r"(b1));
}
__device__ __forceinline__ void cpasync16(uint32_t dst, const void* src) {
    asm volatile("cp.async.cg.shared.global [%0], [%1], 16;" :: "r"(dst), "l"(src));
}
#define CP_COMMIT() asm volatile("cp.async.commit_group;" ::: "memory")
#define CP_WAIT0()  asm volatile("cp.async.wait_group 0;" ::: "memory")

__device__ __forceinline__ float fast_exp2(float x) {
    float y;
    asm("ex2.approx.ftz.f32 %0, %1;" : "=f"(y) : "f"(x));
    return y;
}
__device__ __forceinline__ uint32_t cvt2(float hi, float lo) {   // pack {hi,lo} -> bf16x2
    uint32_t r;
    asm("cvt.rn.bf16x2.f32 %0, %1, %2;" : "=r"(r) : "f"(hi), "f"(lo));
    return r;
}
__device__ __forceinline__ float bfhi_f(uint32_t p) { return __uint_as_float(p & 0xffff0000u); }
__device__ __forceinline__ float bflo_f(uint32_t p) { return __uint_as_float(p << 16); }

// ---------------- prep: w = amp*cos(phase), bascat -----------------------------
__global__ __launch_bounds__(256)
void prep_kernel(const float* __restrict__ pq, const float* __restrict__ aq,
                 const float* __restrict__ pk, const float* __restrict__ ak,
                 const float* __restrict__ pv, const float* __restrict__ av,
                 const float* __restrict__ po, const float* __restrict__ ao,
                 const float* __restrict__ bq, const float* __restrict__ bk,
                 const float* __restrict__ bv) {
    int idx = blockIdx.x * 256 + threadIdx.x;
    if (idx < 4 * HID * HARM) {
        int seg = idx / (HID * HARM);
        int off = idx - seg * (HID * HARM);
        const float* ph = (seg == 0) ? pq : (seg == 1) ? pk : (seg == 2) ? pv : po;
        const float* am = (seg == 0) ? aq : (seg == 1) ? ak : (seg == 2) ? av : ao;
        g_w[idx] = am[off] * cosf(ph[off]);
    } else {
        int j = idx - 4 * HID * HARM;
        if (j < 3 * HARM * HID) {
            int seg = j / (HARM * HID);
            int off = j - seg * (HARM * HID);
            g_bascat[j] = (seg == 0) ? bq[off] : (seg == 1) ? bk[off] : bv[off];
        }
    }
}

// ---------------- G (fp32, transposed store) and C (fp32) ----------------------
__global__ __launch_bounds__(256)
void gc_kernel(const float* __restrict__ bo) {
    int idx = blockIdx.x * 256 + threadIdx.x;
    const float* wq = g_w;
    const float* wk = g_w + HID * HARM;
    const float* wv = g_w + 2 * HID * HARM;
    if (idx < NH * HARM * HARM) {
        int h = idx >> 12, j = (idx >> 6) & 63, k = idx & 63;
        float s = 0.0f;
        for (int d = 0; d < DH; d++)
            s += wq[(h * DH + d) * HARM + k] * wk[(h * DH + d) * HARM + j];
        g_G[(h * HARM + j) * HARM + k] = s;
    } else {
        int e = idx - NH * HARM * HARM;
        if (e < HARM * NH * HARM) {
            int j = e >> 10, hi_ = e & 1023;
            int h = hi_ >> 6, i = hi_ & 63;
            float s = 0.0f;
            for (int d = 0; d < DH; d++)
                s += bo[j * HID + h * DH + d] * wv[(h * DH + d) * HARM + i];
            g_C[j * (NH * HARM) + h * HARM + i] = s;
        }
    }
}

// ---------------- resonance GEMM, fused emission -------------------------------
// R = x @ bascat^T; seg0 -> rq fp32, seg1 -> rk hi/lo, seg2 -> rv^T hi/lo
__global__ __launch_bounds__(256)
void res_kernel(const float* __restrict__ x) {
    __shared__ float As[16][68];
    __shared__ float Bs[16][68];
    const int tx = threadIdx.x, ty = threadIdx.y;
    const int tid = ty * 16 + tx;
    const int m0 = blockIdx.y * 64, n0 = blockIdx.x * 64;
    float acc[4][4] = {};
    for (int k0 = 0; k0 < HID; k0 += 16) {
#pragma unroll
        for (int i = 0; i < 4; i++) {
            int e = tid + i * 256;
            int r = e >> 4, kk = e & 15;
            As[kk][r] = x[(size_t)(m0 + r) * HID + k0 + kk];
            Bs[kk][r] = g_bascat[(size_t)(n0 + r) * HID + k0 + kk];
        }
        __syncthreads();
#pragma unroll
        for (int kk = 0; kk < 16; kk++) {
            float4 a4 = *reinterpret_cast<const float4*>(&As[kk][ty * 4]);
            float4 b4 = *reinterpret_cast<const float4*>(&Bs[kk][tx * 4]);
            float av[4] = {a4.x, a4.y, a4.z, a4.w};
            float bv[4] = {b4.x, b4.y, b4.z, b4.w};
#pragma unroll
            for (int i = 0; i < 4; i++)
#pragma unroll
                for (int j = 0; j < 4; j++)
                    acc[i][j] += av[i] * bv[j];
        }
        __syncthreads();
    }
    const int seg = blockIdx.x;   // 0=q, 1=k, 2=v
#pragma unroll
    for (int i = 0; i < 4; i++) {
        int m = m0 + ty * 4 + i;
        int b = m >> 11, s = m & 2047;
#pragma unroll
        for (int j = 0; j < 4; j++) {
            int jj = tx * 4 + j;
            float v = acc[i][j];
            if (seg == 0) {
                g_resq[(size_t)m * HARM + jj] = v;
            } else if (seg == 1) {
                __nv_bfloat16 hv = __float2bfloat16(v);
                size_t o = (size_t)m * HARM + jj;
                g_rkh[o] = hv;
                g_rkl[o] = __float2bfloat16(v - __bfloat162float(hv));
            } else {
                __nv_bfloat16 hv = __float2bfloat16(v);
                size_t o = ((size_t)b * HARM + jj) * SEQ + s;
                g_rvh[o] = hv;
                g_rvl[o] = __float2bfloat16(v - __bfloat162float(hv));
            }
        }
    }
}

// ---------------- T = K2 * (Res_q @ G^T) -> bf16 hi/lo (b,h,s,64) -------------
__global__ __launch_bounds__(256)
void tproj_kernel() {
    __shared__ float As[16][68];
    __shared__ float Bs[16][68];
    const int tx = threadIdx.x, ty = threadIdx.y;
    const int tid = ty * 16 + tx;
    const int m0 = blockIdx.y * 64, n0 = blockIdx.x * 64;
    const float K2 = 0.12751742f;   // (1/sqrt(128)) * log2(e)
    float acc[4][4] = {};
    for (int k0 = 0; k0 < HARM; k0 += 16) {
#pragma unroll
        for (int i = 0; i < 4; i++) {
            int e = tid + i * 256;
            int r = e >> 4, kk = e & 15;
            As[kk][r] = g_resq[(size_t)(m0 + r) * HARM + k0 + kk];
            Bs[kk][r] = g_G[(size_t)(n0 + r) * HARM + k0 + kk];
        }
        __syncthreads();
#pragma unroll
        for (int kk = 0; kk < 16; kk++) {
            float4 a4 = *reinterpret_cast<const float4*>(&As[kk][ty * 4]);
            float4 b4 = *reinterpret_cast<const float4*>(&Bs[kk][tx * 4]);
            float av[4] = {a4.x, a4.y, a4.z, a4.w};
            float bv[4] = {b4.x, b4.y, b4.z, b4.w};
#pragma unroll
            for (int i = 0; i < 4; i++)
#pragma unroll
                for (int j = 0; j < 4; j++)
                    acc[i][j] += av[i] * bv[j];
        }
        __syncthreads();
    }
#pragma unroll
    for (int i = 0; i < 4; i++) {
        int m = m0 + ty * 4 + i;
        int b = m >> 11, s = m & 2047;
#pragma unroll
        for (int j = 0; j < 4; j++) {
            int n = n0 + tx * 4 + j;
            int h = n >> 6, jj = n & 63;
            size_t idx = (((size_t)(b * NH + h)) * SEQ + s) * HARM + jj;
            float x = acc[i][j] * K2;
            __nv_bfloat16 hv = __float2bfloat16(x);
            g_th[idx] = hv;
            g_tl[idx] = __float2bfloat16(x - __bfloat162float(hv));
        }
    }
}

// ---------------- mma.sync flash attention (T pre-scaled, log2 domain) --------
#define BQ 128
#define BK 64
#define OFF_T  0                  // T hi 16KB, lo 16KB
#define OFF_B0 32768              // double buffers, 32KB: rk_h, rk_l, rv_h, rv_l (8KB each)
#define BUFSZ  32768
#define FA_SMEM (OFF_B0 + 2*BUFSZ)   // 98304

__device__ __forceinline__ void prefetch_tile(uint32_t sb, int buf, int b, int kt, int tid) {
    const uint32_t base = sb + OFF_B0 + buf * BUFSZ;
    const __nv_bfloat16* rk_h = g_rkh + ((size_t)b * SEQ + kt * BK) * HARM;
    const __nv_bfloat16* rk_l = g_rkl + ((size_t)b * SEQ + kt * BK) * HARM;
#pragma unroll
    for (int i = 0; i < 2; i++) {
        int e = tid + i * 256;
        int row = e >> 3, cb = e & 7;                  // 64 rows x 8 chunks
        uint32_t off = row * 128 + ((cb ^ (row & 7)) << 4);
        cpasync16(base + off,        rk_h + row * HARM + cb * 8);
        cpasync16(base + 8192 + off, rk_l + row * HARM + cb * 8);
    }
    const __nv_bfloat16* rv_h = g_rvh + (size_t)b * HARM * SEQ + kt * BK;
    const __nv_bfloat16* rv_l = g_rvl + (size_t)b * HARM * SEQ + kt * BK;
#pragma unroll
    for (int i = 0; i < 2; i++) {
        int e = tid + i * 256;
        int row = e >> 3, cb = e & 7;                  // 64 rows (j) x 8 chunks (keys)
        uint32_t off = row * 128 + ((cb ^ (row & 7)) << 4);
        cpasync16(base + 16384 + off, rv_h + (size_t)row * SEQ + cb * 8);
        cpasync16(base + 24576 + off, rv_l + (size_t)row * SEQ + cb * 8);
    }
    CP_COMMIT();
}

__global__ __launch_bounds__(256, 2)
void flash_mma_kernel() {
    extern __shared__ char sm[];
    const uint32_t sb = smem_u32(sm);
    const int tid = threadIdx.x;
    const int lane = tid & 31, w = tid >> 5;
    const int bh = blockIdx.y;
    const int q0 = blockIdx.x * BQ;
    const int b = bh >> 4, h = bh & 15;

    // ---- stage T tile (128 x 64 bf16 hi/lo, swizzled 128B rows) ----
    {
        const __nv_bfloat16* th = g_th + ((size_t)bh * SEQ + q0) * HARM;
        const __nv_bfloat16* tl = g_tl + ((size_t)bh * SEQ + q0) * HARM;
#pragma unroll
        for (int i = 0; i < 4; i++) {
            int e = tid + i * 256;
            int row = e >> 3, cb = e & 7;
            uint32_t off = row * 128 + ((cb ^ (row & 7)) << 4);
            *reinterpret_cast<uint4*>(sm + OFF_T + off) =
                *reinterpret_cast<const uint4*>(th + row * HARM + cb * 8);
            *reinterpret_cast<uint4*>(sm + OFF_T + 16384 + off) =
                *reinterpret_cast<const uint4*>(tl + row * HARM + cb * 8);
        }
    }
    prefetch_tile(sb, 0, b, 0, tid);
    __syncthreads();

    float U[8][4] = {};
    float rs0 = 0.0f, rs1 = 0.0f;
    float mx0 = -3.0e38f, mx1 = -3.0e38f;
    int buf = 0;

    for (int kt = 0; kt < SEQ / BK; kt++) {
        CP_WAIT0();
        __syncthreads();
        if (kt + 1 < SEQ / BK) prefetch_tile(sb, buf ^ 1, b, kt + 1, tid);

        const uint32_t kb = sb + OFF_B0 + buf * BUFSZ;

        // ---- S = T Res_k^T (hi*hi + lo*hi + hi*lo), K=64 ----
        float S[8][4] = {};
#pragma unroll
        for (int ks = 0; ks < 4; ks++) {
            int rowA = 16 * w + (lane & 15);
            int cbA = 2 * ks + (lane >> 4);
            uint32_t offA = rowA * 128 + ((cbA ^ (rowA & 7)) << 4);
            uint32_t th[4], tl[4];
            ldsm4(th, sb + OFF_T + offA);
            ldsm4(tl, sb + OFF_T + 16384 + offA);
#pragma unroll
            for (int nb = 0; nb < 4; nb++) {
                int rowB = nb * 16 + (lane & 15);
                uint32_t offB = rowB * 128 + (((2 * ks + (lane >> 4)) ^ (rowB & 7)) << 4);
                uint32_t kh[4], kl[4];
                ldsm4(kh, kb + offB);
                ldsm4(kl, kb + 8192 + offB);
                mma16816(S[2 * nb],     th, kh[0], kh[2]);
                mma16816(S[2 * nb + 1], th, kh[1], kh[3]);
                mma16816(S[2 * nb],     tl, kh[0], kh[2]);
                mma16816(S[2 * nb + 1], tl, kh[1], kh[3]);
                mma16816(S[2 * nb],     th, kl[0], kl[2]);
                mma16816(S[2 * nb + 1], th, kl[1], kl[3]);
            }
        }

        // ---- online softmax (S already in log2 domain) ----
        float tm0 = -3.0e38f, tm1 = -3.0e38f;
#pragma unroll
        for (int t = 0; t < 8; t++) {
            tm0 = fmaxf(tm0, fmaxf(S[t][0], S[t][1]));
            tm1 = fmaxf(tm1, fmaxf(S[t][2], S[t][3]));
        }
        tm0 = fmaxf(tm0, __shfl_xor_sync(0xffffffffu, tm0, 1));
        tm0 = fmaxf(tm0, __shfl_xor_sync(0xffffffffu, tm0, 2));
        tm1 = fmaxf(tm1, __shfl_xor_sync(0xffffffffu, tm1, 1));
        tm1 = fmaxf(tm1, __shfl_xor_sync(0xffffffffu, tm1, 2));

        float nm0 = fmaxf(mx0, tm0);
        float nm1 = fmaxf(mx1, tm1);
        float c0 = fast_exp2(mx0 - nm0);
        float c1 = fast_exp2(mx1 - nm1);
        mx0 = nm0; mx1 = nm1;

        float ls0 = 0.0f, ls1 = 0.0f;
#pragma unroll
        for (int t = 0; t < 8; t++) {
            float e0 = fast_exp2(S[t][0] - nm0);
            float e1 = fast_exp2(S[t][1] - nm0);
            float e2 = fast_exp2(S[t][2] - nm1);
            float e3 = fast_exp2(S[t][3] - nm1);
            ls0 += e0 + e1;
            ls1 += e2 + e3;
            S[t][0] = e0; S[t][1] = e1; S[t][2] = e2; S[t][3] = e3;
        }
        rs0 = rs0 * c0 + ls0;
        rs1 = rs1 * c1 + ls1;
#pragma unroll
        for (int t = 0; t < 8; t++) {
            U[t][0] *= c0; U[t][1] *= c0;
            U[t][2] *= c1; U[t][3] *= c1;
        }

        // ---- U += P Res_v (P in registers as A-fragments), N=64 ----
#pragma unroll
        for (int ks2 = 0; ks2 < 4; ks2++) {
            uint32_t ph[4], pl[4];
            ph[0] = cvt2(S[2 * ks2][1],     S[2 * ks2][0]);
            ph[1] = cvt2(S[2 * ks2][3],     S[2 * ks2][2]);
            ph[2] = cvt2(S[2 * ks2 + 1][1], S[2 * ks2 + 1][0]);
            ph[3] = cvt2(S[2 * ks2 + 1][3], S[2 * ks2 + 1][2]);
            pl[0] = cvt2(S[2 * ks2][1]     - bfhi_f(ph[0]), S[2 * ks2][0]     - bflo_f(ph[0]));
            pl[1] = cvt2(S[2 * ks2][3]     - bfhi_f(ph[1]), S[2 * ks2][2]     - bflo_f(ph[1]));
            pl[2] = cvt2(S[2 * ks2 + 1][1] - bfhi_f(ph[2]), S[2 * ks2 + 1][0] - bflo_f(ph[2]));
            pl[3] = cvt2(S[2 * ks2 + 1][3] - bfhi_f(ph[3]), S[2 * ks2 + 1][2] - bflo_f(ph[3]));
#pragma unroll
            for (int nb = 0; nb < 4; nb++) {
                int rowB = nb * 16 + (lane & 15);
                uint32_t offB = rowB * 128 + (((2 * ks2 + (lane >> 4)) ^ (rowB & 7)) << 4);
                uint32_t vh[4], vl[4];
                ldsm4(vh, kb + 16384 + offB);
                ldsm4(vl, kb + 24576 + offB);
                mma16816(U[2 * nb],     ph, vh[0], vh[2]);
                mma16816(U[2 * nb + 1], ph, vh[1], vh[3]);
                mma16816(U[2 * nb],     ph, vl[0], vl[2]);
                mma16816(U[2 * nb + 1], ph, vl[1], vl[3]);
                mma16816(U[2 * nb],     pl, vh[0], vh[2]);
                mma16816(U[2 * nb + 1], pl, vh[1], vh[3]);
            }
        }
        buf ^= 1;
    }

    // ---- epilogue: normalize, store U to (b,s,h,64) fp32 ----
    rs0 += __shfl_xor_sync(0xffffffffu, rs0, 1);
    rs0 += __shfl_xor_sync(0xffffffffu, rs0, 2);
    rs1 += __shfl_xor_sync(0xffffffffu, rs1, 1);
    rs1 += __shfl_xor_sync(0xffffffffu, rs1, 2);
    const float inv0 = 1.0f / rs0;
    const float inv1 = 1.0f / rs1;

    const int row0 = q0 + 16 * w + (lane >> 2);
    float* u0 = g_u + (((size_t)b * SEQ + row0) * NH + h) * HARM + (lane & 3) * 2;
    float* u1 = u0 + 8 * (size_t)NH * HARM;
#pragma unroll
    for (int nb = 0; nb < 4; nb++) {
        *reinterpret_cast<float2*>(u0 + nb * 16) =
            make_float2(U[2 * nb][0] * inv0, U[2 * nb][1] * inv0);
        *reinterpret_cast<float2*>(u1 + nb * 16) =
            make_float2(U[2 * nb][2] * inv1, U[2 * nb][3] * inv1);
        *reinterpret_cast<float2*>(u0 + nb * 16 + 8) =
            make_float2(U[2 * nb + 1][0] * inv0, U[2 * nb + 1][1] * inv0);
        *reinterpret_cast<float2*>(u1 + nb * 16 + 8) =
            make_float2(U[2 * nb + 1][2] * inv1, U[2 * nb + 1][3] * inv1);
    }
}

// ---------------- res_o partials, split-K x4 -----------------------------------
__global__ __launch_bounds__(256)
void uproj_kernel() {
    __shared__ float As[16][68];
    __shared__ float Bs[16][68];
    const int tx = threadIdx.x, ty = threadIdx.y;
    const int tid = ty * 16 + tx;
    const int m0 = blockIdx.y * 64;
    const int kc = blockIdx.x;
    const int kbase = kc * 256;
    float acc[4][4] = {};
    for (int k0 = 0; k0 < 256; k0 += 16) {
#pragma unroll
        for (int i = 0; i < 4; i++) {
            int e = tid + i * 256;
            int r = e >> 4, kk = e & 15;
            As[kk][r] = g_u[(size_t)(m0 + r) * (NH * HARM) + kbase + k0 + kk];
            Bs[kk][r] = g_C[(size_t)r * (NH * HARM) + kbase + k0 + kk];
        }
        __syncthreads();
#pragma unroll
        for (int kk = 0; kk < 16; kk++) {
            float4 a4 = *reinterpret_cast<const float4*>(&As[kk][ty * 4]);
            float4 b4 = *reinterpret_cast<const float4*>(&Bs[kk][tx * 4]);
            float av[4] = {a4.x, a4.y, a4.z, a4.w};
            float bv[4] = {b4.x, b4.y, b4.z, b4.w};
#pragma unroll
            for (int i = 0; i < 4; i++)
#pragma unroll
                for (int j = 0; j < 4; j++)
                    acc[i][j] += av[i] * bv[j];
        }
        __syncthreads();
    }
    float* out = g_reso4 + (size_t)kc * MTOT * HARM;
#pragma unroll
    for (int i = 0; i < 4; i++) {
        int m = m0 + ty * 4 + i;
#pragma unroll
        for (int j = 0; j < 4; j++)
            out[(size_t)m * HARM + tx * 4 + j] = acc[i][j];
    }
}

// ---------------- out = (sum of partials) @ Wo^T -------------------------------
__global__ __launch_bounds__(256)
void out_kernel(float* __restrict__ C) {
    __shared__ float As[16][68];
    __shared__ float Bs[16][68];
    const int tx = threadIdx.x, ty = threadIdx.y;
    const int tid = ty * 16 + tx;
    const int m0 = blockIdx.y * 64, n0 = blockIdx.x * 64;
    const float* wo = g_w + 3 * HID * HARM;
    float acc[4][4] = {};
    for (int k0 = 0; k0 < HARM; k0 += 16) {
#pragma unroll
        for (int i = 0; i < 4; i++) {
            int e = tid + i * 256;
            int r = e >> 4, kk = e & 15;
            size_t o = (size_t)(m0 + r) * HARM + k0 + kk;
            As[kk][r] = g_reso4[o] + g_reso4[o + (size_t)MTOT * HARM]
                      + g_reso4[o + 2 * (size_t)MTOT * HARM]
                      + g_reso4[o + 3 * (size_t)MTOT * HARM];
            Bs[kk][r] = wo[(size_t)(n0 + r) * HARM + k0 + kk];
        }
        __syncthreads();
#pragma unroll
        for (int kk = 0; kk < 16; kk++) {
            float4 a4 = *reinterpret_cast<const float4*>(&As[kk][ty * 4]);
            float4 b4 = *reinterpret_cast<const float4*>(&Bs[kk][tx * 4]);
            float av[4] = {a4.x, a4.y, a4.z, a4.w};
            float bv[4] = {b4.x, b4.y, b4.z, b4.w};
#pragma unroll
            for (int i = 0; i < 4; i++)
#pragma unroll
                for (int j = 0; j < 4; j++)
                    acc[i][j] += av[i] * bv[j];
        }
        __syncthreads();
    }
#pragma unroll
    for (int i = 0; i < 4; i++) {
        int m = m0 + ty * 4 + i;
#pragma unroll
        for (int j = 0; j < 4; j++)
            C[(size_t)m * HID + n0 + tx * 4 + j] = acc[i][j];
    }
}

// ---------------- launcher ----------------------------------------------------
extern "C" void kernel_launch(void* const* d_in, const int* in_sizes, int n_in,
                              void* d_out, int out_size) {
    const float* x  = (const float*)d_in[0];
    const float* bq = (const float*)d_in[1];
    const float* pq = (const float*)d_in[2];
    const float* aq = (const float*)d_in[3];
    const float* bk = (const float*)d_in[4];
    const float* pk = (const float*)d_in[5];
    const float* ak = (const float*)d_in[6];
    const float* bv = (const float*)d_in[7];
    const float* pv = (const float*)d_in[8];
    const float* av = (const float*)d_in[9];
    const float* bo = (const float*)d_in[10];
    const float* po = (const float*)d_in[11];
    const float* ao = (const float*)d_in[12];
    float* out = (float*)d_out;

    // 1: weights + basis concat
    prep_kernel<<<(7 * HID * HARM + 255) / 256, 256>>>(pq, aq, pk, ak, pv, av, po, ao,
                                                       bq, bk, bv);
    // 2: per-head G and C (fp32)
    gc_kernel<<<(2 * NH * HARM * HARM + 255) / 256, 256>>>(bo);

    dim3 thr(16, 16);
    // 3: resonances; rq fp32, rk/rv bf16 hi/lo (rv transposed)
    res_kernel<<<dim3(3, MTOT / 64), thr>>>(x);
    // 4: T = K2 * Res_q G^T -> bf16 hi/lo
    tproj_kernel<<<dim3(NH * HARM / 64, MTOT / 64), thr>>>();

    // 5: attention
    cudaFuncSetAttribute(flash_mma_kernel,
                         cudaFuncAttributeMaxDynamicSharedMemorySize, FA_SMEM);
    flash_mma_kernel<<<dim3(SEQ / BQ, BATCH * NH), 256, FA_SMEM>>>();

    // 6: res_o partials (split-K x4)
    uproj_kernel<<<dim3(4, MTOT / 64), thr>>>();
    // 7: out = res_o @ Wo^T
    out_kernel<<<dim3(HID / 64, MTOT / 64), thr>>>(out);
}

// round 13
// speedup vs baseline: 1.6488x; 1.6488x over previous
#include <cuda_runtime.h>
#include <cuda_bf16.h>
#include <cstdint>

#define HID   2048
#define NH    16
#define DH    128
#define HARM  64
#define BATCH 2
#define SEQ   2048
#define MTOT  (BATCH*SEQ)   // 4096

// ---------------- scratch (static device globals; no allocs allowed) --------
__device__ float g_resq[MTOT * HARM];          // Res_q fp32 (for tproj)
__device__ float g_G[NH * HARM * HARM];        // G[(h,j)][k] = (Wq_h^T Wk_h)[k,j]
__device__ float g_C[HARM * NH * HARM];        // C[j][(h,i)] = (Bo_h Wv_h)[j,i]
__device__ float g_wo[HID * HARM];             // amp_o*cos(phase_o)
__device__ __align__(256) __nv_bfloat16 g_th[MTOT * NH * HARM];  // T hi (b,h,s,64), K2-scaled
__device__ __align__(256) __nv_bfloat16 g_tl[MTOT * NH * HARM];
__device__ __align__(256) __nv_bfloat16 g_rkh[MTOT * HARM];      // Res_k hi (b,s,64)
__device__ __align__(256) __nv_bfloat16 g_rkl[MTOT * HARM];
__device__ __align__(256) __nv_bfloat16 g_rvh[MTOT * HARM];      // Res_v^T hi (b,64,s)
__device__ __align__(256) __nv_bfloat16 g_rvl[MTOT * HARM];
__device__ __align__(256) float g_u[MTOT * NH * HARM];           // U (b,s,h,64) fp32
__device__ float g_reso4[4 * MTOT * HARM];     // split-K partials of res_o

// ---------------- PTX helpers (portable: sm_80+ features only) ---------------
__device__ __forceinline__ uint32_t smem_u32(const void* p) {
    uint32_t a;
    asm("{ .reg .u64 t; cvta.to.shared.u64 t, %1; cvt.u32.u64 %0, t; }" : "=r"(a) : "l"(p));
    return a;
}
__device__ __forceinline__ void ldsm4(uint32_t r[4], uint32_t addr) {
    asm volatile("ldmatrix.sync.aligned.m8n8.x4.shared.b16 {%0,%1,%2,%3}, [%4];"
                 : "=r"(r[0]), "=r"(r[1]), "=r"(r[2]), "=r"(r[3]) : "r"(addr));
}
__device__ __forceinline__ void mma16816(float d[4], const uint32_t a[4],
                                         uint32_t b0, uint32_t b1) {
    asm volatile("mma.sync.aligned.m16n8k16.row.col.f32.bf16.bf16.f32 "
                 "{%0,%1,%2,%3}, {%4,%5,%6,%7}, {%8,%9}, {%0,%1,%2,%3};"
                 : "+f"(d[0]), "+f"(d[1]), "+f"(d[2]), "+f"(d[3])
                 : "r"(a[0]), "r"(a[1]), "r"(a[2]), "r"(a[3]), "r"(b0), "r"(b1));
}
__device__ __forceinline__ void cpasync16(uint32_t dst, const void* src) {
    asm volatile("cp.async.cg.shared.global [%0], [%1], 16;" :: "r"(dst), "l"(src));
}
#define CP_COMMIT() asm volatile("cp.async.commit_group;" ::: "memory")
#define CP_WAIT0()  asm volatile("cp.async.wait_group 0;" ::: "memory")

__device__ __forceinline__ float fast_exp2(float x) {
    float y;
    asm("ex2.approx.ftz.f32 %0, %1;" : "=f"(y) : "f"(x));
    return y;
}
__device__ __forceinline__ uint32_t cvt2(float hi, float lo) {   // pack {hi,lo} -> bf16x2
    uint32_t r;
    asm("cvt.rn.bf16x2.f32 %0, %1, %2;" : "=r"(r) : "f"(hi), "f"(lo));
    return r;
}
__device__ __forceinline__ float bfhi_f(uint32_t p) { return __uint_as_float(p & 0xffff0000u); }
__device__ __forceinline__ float bflo_f(uint32_t p) { return __uint_as_float(p << 16); }

// ---------------- launch 1: G and C with inline w = amp*cos(phase) -------------
// blocks 0..15: G for head h = blockIdx.x
// blocks 16..31: C for head h = blockIdx.x - 16
__global__ __launch_bounds__(256)
void gc_kernel(const float* __restrict__ pq, const float* __restrict__ aq,
               const float* __restrict__ pk, const float* __restrict__ ak,
               const float* __restrict__ pv, const float* __restrict__ av,
               const float* __restrict__ bo) {
    __shared__ float sA[64][68];
    __shared__ float sB[64][68];
    const int tx = threadIdx.x, ty = threadIdx.y;
    const int tid = ty * 16 + tx;
    const bool isG = blockIdx.x < 16;
    const int h = isG ? blockIdx.x : blockIdx.x - 16;
    float acc[4][4] = {};

    for (int d0 = 0; d0 < DH; d0 += 64) {
        __syncthreads();
        if (isG) {
            // sA[d][k] = wq(d0+d, k), sB[d][j] = wk(d0+d, j)
#pragma unroll
            for (int i = 0; i < 16; i++) {
                int e = tid + i * 256;
                int d = e >> 6, c = e & 63;
                size_t o = (size_t)(h * DH + d0 + d) * HARM + c;
                sA[d][c] = aq[o] * __cosf(pq[o]);
                sB[d][c] = ak[o] * __cosf(pk[o]);
            }
        } else {
            // sA[d][j] = bo[j, h*128 + d0+d] (transposed), sB[d][i] = wv(d0+d, i)
#pragma unroll
            for (int i = 0; i < 16; i++) {
                int e = tid + i * 256;
                int j = e >> 6, d = e & 63;
                sA[d][j] = bo[(size_t)j * HID + h * DH + d0 + d];
            }
#pragma unroll
            for (int i = 0; i < 16; i++) {
                int e = tid + i * 256;
                int d = e >> 6, c = e & 63;
                size_t o = (size_t)(h * DH + d0 + d) * HARM + c;
                sB[d][c] = av[o] * __cosf(pv[o]);
            }
        }
        __syncthreads();
#pragma unroll 8
        for (int dd = 0; dd < 64; dd++) {
            // G: rows = j (ty), cols = k (tx):  acc[j][k] += wk(d,j)*wq(d,k)
            // C: rows = j (ty), cols = i (tx):  acc[j][i] += bo(j,d)*wv(d,i)
            float4 a4 = *reinterpret_cast<const float4*>(isG ? &sB[dd][ty * 4] : &sA[dd][ty * 4]);
            float4 b4 = *reinterpret_cast<const float4*>(isG ? &sA[dd][tx * 4] : &sB[dd][tx * 4]);
            float av_[4] = {a4.x, a4.y, a4.z, a4.w};
            float bv_[4] = {b4.x, b4.y, b4.z, b4.w};
#pragma unroll
            for (int i = 0; i < 4; i++)
#pragma unroll
                for (int j = 0; j < 4; j++)
                    acc[i][j] += av_[i] * bv_[j];
        }
    }
#pragma unroll
    for (int i = 0; i < 4; i++) {
        int r = ty * 4 + i;
#pragma unroll
        for (int j = 0; j < 4; j++) {
            int c = tx * 4 + j;
            if (isG) g_G[((size_t)h * HARM + r) * HARM + c] = acc[i][j];
            else     g_C[(size_t)r * (NH * HARM) + h * HARM + c] = acc[i][j];
        }
    }
}

// ---------------- launch 2: resonances (raw basis pointers) --------------------
// seg0 -> rq fp32, seg1 -> rk hi/lo, seg2 -> rv^T hi/lo
__global__ __launch_bounds__(256)
void res_kernel(const float* __restrict__ x, const float* __restrict__ bq,
                const float* __restrict__ bk, const float* __restrict__ bv) {
    __shared__ float As[16][68];
    __shared__ float Bs[16][68];
    const int tx = threadIdx.x, ty = threadIdx.y;
    const int tid = ty * 16 + tx;
    const int m0 = blockIdx.y * 64;
    const int seg = blockIdx.x;   // 0=q, 1=k, 2=v
    const float* bsrc = (seg == 0) ? bq : (seg == 1) ? bk : bv;
    float acc[4][4] = {};
    for (int k0 = 0; k0 < HID; k0 += 16) {
#pragma unroll
        for (int i = 0; i < 4; i++) {
            int e = tid + i * 256;
            int r = e >> 4, kk = e & 15;
            As[kk][r] = x[(size_t)(m0 + r) * HID + k0 + kk];
            Bs[kk][r] = bsrc[(size_t)r * HID + k0 + kk];
        }
        __syncthreads();
#pragma unroll
        for (int kk = 0; kk < 16; kk++) {
            float4 a4 = *reinterpret_cast<const float4*>(&As[kk][ty * 4]);
            float4 b4 = *reinterpret_cast<const float4*>(&Bs[kk][tx * 4]);
            float av[4] = {a4.x, a4.y, a4.z, a4.w};
            float bv_[4] = {b4.x, b4.y, b4.z, b4.w};
#pragma unroll
            for (int i = 0; i < 4; i++)
#pragma unroll
                for (int j = 0; j < 4; j++)
                    acc[i][j] += av[i] * bv_[j];
        }
        __syncthreads();
    }
#pragma unroll
    for (int i = 0; i < 4; i++) {
        int m = m0 + ty * 4 + i;
        int b = m >> 11, s = m & 2047;
#pragma unroll
        for (int j = 0; j < 4; j++) {
            int jj = tx * 4 + j;
            float v = acc[i][j];
            if (seg == 0) {
                g_resq[(size_t)m * HARM + jj] = v;
            } else if (seg == 1) {
                __nv_bfloat16 hv = __float2bfloat16(v);
                size_t o = (size_t)m * HARM + jj;
                g_rkh[o] = hv;
                g_rkl[o] = __float2bfloat16(v - __bfloat162float(hv));
            } else {
                __nv_bfloat16 hv = __float2bfloat16(v);
                size_t o = ((size_t)b * HARM + jj) * SEQ + s;
                g_rvh[o] = hv;
                g_rvl[o] = __float2bfloat16(v - __bfloat162float(hv));
            }
        }
    }
}

// ---------------- launch 3: T = K2 * (Res_q @ G^T) -> bf16 hi/lo ---------------
__global__ __launch_bounds__(256)
void tproj_kernel() {
    __shared__ float As[16][68];
    __shared__ float Bs[16][68];
    const int tx = threadIdx.x, ty = threadIdx.y;
    const int tid = ty * 16 + tx;
    const int m0 = blockIdx.y * 64, n0 = blockIdx.x * 64;
    const float K2 = 0.12751742f;   // (1/sqrt(128)) * log2(e)
    float acc[4][4] = {};
    for (int k0 = 0; k0 < HARM; k0 += 16) {
#pragma unroll
        for (int i = 0; i < 4; i++) {
            int e = tid + i * 256;
            int r = e >> 4, kk = e & 15;
            As[kk][r] = g_resq[(size_t)(m0 + r) * HARM + k0 + kk];
            Bs[kk][r] = g_G[(size_t)(n0 + r) * HARM + k0 + kk];
        }
        __syncthreads();
#pragma unroll
        for (int kk = 0; kk < 16; kk++) {
            float4 a4 = *reinterpret_cast<const float4*>(&As[kk][ty * 4]);
            float4 b4 = *reinterpret_cast<const float4*>(&Bs[kk][tx * 4]);
            float av[4] = {a4.x, a4.y, a4.z, a4.w};
            float bv[4] = {b4.x, b4.y, b4.z, b4.w};
#pragma unroll
            for (int i = 0; i < 4; i++)
#pragma unroll
                for (int j = 0; j < 4; j++)
                    acc[i][j] += av[i] * bv[j];
        }
        __syncthreads();
    }
#pragma unroll
    for (int i = 0; i < 4; i++) {
        int m = m0 + ty * 4 + i;
        int b = m >> 11, s = m & 2047;
#pragma unroll
        for (int j = 0; j < 4; j++) {
            int n = n0 + tx * 4 + j;
            int h = n >> 6, jj = n & 63;
            size_t idx = (((size_t)(b * NH + h)) * SEQ + s) * HARM + jj;
            float v = acc[i][j] * K2;
            __nv_bfloat16 hv = __float2bfloat16(v);
            g_th[idx] = hv;
            g_tl[idx] = __float2bfloat16(v - __bfloat162float(hv));
        }
    }
}

// ---------------- launch 4: flash attention (profiled slot) --------------------
#define BQ 128
#define BK 64
#define OFF_T  0                  // T hi 16KB, lo 16KB
#define OFF_B0 32768              // double buffers, 32KB: rk_h, rk_l, rv_h, rv_l (8KB each)
#define BUFSZ  32768
#define FA_SMEM (OFF_B0 + 2*BUFSZ)   // 98304

__device__ __forceinline__ void prefetch_tile(uint32_t sb, int buf, int b, int kt, int tid) {
    const uint32_t base = sb + OFF_B0 + buf * BUFSZ;
    const __nv_bfloat16* rk_h = g_rkh + ((size_t)b * SEQ + kt * BK) * HARM;
    const __nv_bfloat16* rk_l = g_rkl + ((size_t)b * SEQ + kt * BK) * HARM;
#pragma unroll
    for (int i = 0; i < 2; i++) {
        int e = tid + i * 256;
        int row = e >> 3, cb = e & 7;                  // 64 rows x 8 chunks
        uint32_t off = row * 128 + ((cb ^ (row & 7)) << 4);
        cpasync16(base + off,        rk_h + row * HARM + cb * 8);
        cpasync16(base + 8192 + off, rk_l + row * HARM + cb * 8);
    }
    const __nv_bfloat16* rv_h = g_rvh + (size_t)b * HARM * SEQ + kt * BK;
    const __nv_bfloat16* rv_l = g_rvl + (size_t)b * HARM * SEQ + kt * BK;
#pragma unroll
    for (int i = 0; i < 2; i++) {
        int e = tid + i * 256;
        int row = e >> 3, cb = e & 7;                  // 64 rows (j) x 8 chunks (keys)
        uint32_t off = row * 128 + ((cb ^ (row & 7)) << 4);
        cpasync16(base + 16384 + off, rv_h + (size_t)row * SEQ + cb * 8);
        cpasync16(base + 24576 + off, rv_l + (size_t)row * SEQ + cb * 8);
    }
    CP_COMMIT();
}

__global__ __launch_bounds__(256, 2)
void flash_mma_kernel() {
    extern __shared__ char sm[];
    const uint32_t sb = smem_u32(sm);
    const int tid = threadIdx.x;
    const int lane = tid & 31, w = tid >> 5;
    const int bh = blockIdx.y;
    const int q0 = blockIdx.x * BQ;
    const int b = bh >> 4, h = bh & 15;

    // ---- stage T tile (128 x 64 bf16 hi/lo, swizzled 128B rows) ----
    {
        const __nv_bfloat16* th = g_th + ((size_t)bh * SEQ + q0) * HARM;
        const __nv_bfloat16* tl = g_tl + ((size_t)bh * SEQ + q0) * HARM;
#pragma unroll
        for (int i = 0; i < 4; i++) {
            int e = tid + i * 256;
            int row = e >> 3, cb = e & 7;
            uint32_t off = row * 128 + ((cb ^ (row & 7)) << 4);
            *reinterpret_cast<uint4*>(sm + OFF_T + off) =
                *reinterpret_cast<const uint4*>(th + row * HARM + cb * 8);
            *reinterpret_cast<uint4*>(sm + OFF_T + 16384 + off) =
                *reinterpret_cast<const uint4*>(tl + row * HARM + cb * 8);
        }
    }
    prefetch_tile(sb, 0, b, 0, tid);
    __syncthreads();

    float U[8][4] = {};
    float rs0 = 0.0f, rs1 = 0.0f;
    float mx0 = -3.0e38f, mx1 = -3.0e38f;
    int buf = 0;

    for (int kt = 0; kt < SEQ / BK; kt++) {
        CP_WAIT0();
        __syncthreads();
        if (kt + 1 < SEQ / BK) prefetch_tile(sb, buf ^ 1, b, kt + 1, tid);

        const uint32_t kb = sb + OFF_B0 + buf * BUFSZ;

        // ---- S = T Res_k^T (hi*hi + lo*hi + hi*lo), K=64 ----
        float S[8][4] = {};
#pragma unroll
        for (int ks = 0; ks < 4; ks++) {
            int rowA = 16 * w + (lane & 15);
            int cbA = 2 * ks + (lane >> 4);
            uint32_t offA = rowA * 128 + ((cbA ^ (rowA & 7)) << 4);
            uint32_t th[4], tl[4];
            ldsm4(th, sb + OFF_T + offA);
            ldsm4(tl, sb + OFF_T + 16384 + offA);
#pragma unroll
            for (int nb = 0; nb < 4; nb++) {
                int rowB = nb * 16 + (lane & 15);
                uint32_t offB = rowB * 128 + (((2 * ks + (lane >> 4)) ^ (rowB & 7)) << 4);
                uint32_t kh[4], kl[4];
                ldsm4(kh, kb + offB);
                ldsm4(kl, kb + 8192 + offB);
                mma16816(S[2 * nb],     th, kh[0], kh[2]);
                mma16816(S[2 * nb + 1], th, kh[1], kh[3]);
                mma16816(S[2 * nb],     tl, kh[0], kh[2]);
                mma16816(S[2 * nb + 1], tl, kh[1], kh[3]);
                mma16816(S[2 * nb],     th, kl[0], kl[2]);
                mma16816(S[2 * nb + 1], th, kl[1], kl[3]);
            }
        }

        // ---- online softmax (S already in log2 domain) ----
        float tm0 = -3.0e38f, tm1 = -3.0e38f;
#pragma unroll
        for (int t = 0; t < 8; t++) {
            tm0 = fmaxf(tm0, fmaxf(S[t][0], S[t][1]));
            tm1 = fmaxf(tm1, fmaxf(S[t][2], S[t][3]));
        }
        tm0 = fmaxf(tm0, __shfl_xor_sync(0xffffffffu, tm0, 1));
        tm0 = fmaxf(tm0, __shfl_xor_sync(0xffffffffu, tm0, 2));
        tm1 = fmaxf(tm1, __shfl_xor_sync(0xffffffffu, tm1, 1));
        tm1 = fmaxf(tm1, __shfl_xor_sync(0xffffffffu, tm1, 2));

        float nm0 = fmaxf(mx0, tm0);
        float nm1 = fmaxf(mx1, tm1);
        float c0 = fast_exp2(mx0 - nm0);
        float c1 = fast_exp2(mx1 - nm1);
        mx0 = nm0; mx1 = nm1;

        float ls0 = 0.0f, ls1 = 0.0f;
#pragma unroll
        for (int t = 0; t < 8; t++) {
            float e0 = fast_exp2(S[t][0] - nm0);
            float e1 = fast_exp2(S[t][1] - nm0);
            float e2 = fast_exp2(S[t][2] - nm1);
            float e3 = fast_exp2(S[t][3] - nm1);
            ls0 += e0 + e1;
            ls1 += e2 + e3;
            S[t][0] = e0; S[t][1] = e1; S[t][2] = e2; S[t][3] = e3;
        }
        rs0 = rs0 * c0 + ls0;
        rs1 = rs1 * c1 + ls1;
#pragma unroll
        for (int t = 0; t < 8; t++) {
            U[t][0] *= c0; U[t][1] *= c0;
            U[t][2] *= c1; U[t][3] *= c1;
        }

        // ---- U += P Res_v (P in registers as A-fragments), N=64 ----
#pragma unroll
        for (int ks2 = 0; ks2 < 4; ks2++) {
            uint32_t ph[4], pl[4];
            ph[0] = cvt2(S[2 * ks2][1],     S[2 * ks2][0]);
            ph[1] = cvt2(S[2 * ks2][3],     S[2 * ks2][2]);
            ph[2] = cvt2(S[2 * ks2 + 1][1], S[2 * ks2 + 1][0]);
            ph[3] = cvt2(S[2 * ks2 + 1][3], S[2 * ks2 + 1][2]);
            pl[0] = cvt2(S[2 * ks2][1]     - bfhi_f(ph[0]), S[2 * ks2][0]     - bflo_f(ph[0]));
            pl[1] = cvt2(S[2 * ks2][3]     - bfhi_f(ph[1]), S[2 * ks2][2]     - bflo_f(ph[1]));
            pl[2] = cvt2(S[2 * ks2 + 1][1] - bfhi_f(ph[2]), S[2 * ks2 + 1][0] - bflo_f(ph[2]));
            pl[3] = cvt2(S[2 * ks2 + 1][3] - bfhi_f(ph[3]), S[2 * ks2 + 1][2] - bflo_f(ph[3]));
#pragma unroll
            for (int nb = 0; nb < 4; nb++) {
                int rowB = nb * 16 + (lane & 15);
                uint32_t offB = rowB * 128 + (((2 * ks2 + (lane >> 4)) ^ (rowB & 7)) << 4);
                uint32_t vh[4], vl[4];
                ldsm4(vh, kb + 16384 + offB);
                ldsm4(vl, kb + 24576 + offB);
                mma16816(U[2 * nb],     ph, vh[0], vh[2]);
                mma16816(U[2 * nb + 1], ph, vh[1], vh[3]);
                mma16816(U[2 * nb],     ph, vl[0], vl[2]);
                mma16816(U[2 * nb + 1], ph, vl[1], vl[3]);
                mma16816(U[2 * nb],     pl, vh[0], vh[2]);
                mma16816(U[2 * nb + 1], pl, vh[1], vh[3]);
            }
        }
        buf ^= 1;
    }

    // ---- epilogue: normalize, store U to (b,s,h,64) fp32 ----
    rs0 += __shfl_xor_sync(0xffffffffu, rs0, 1);
    rs0 += __shfl_xor_sync(0xffffffffu, rs0, 2);
    rs1 += __shfl_xor_sync(0xffffffffu, rs1, 1);
    rs1 += __shfl_xor_sync(0xffffffffu, rs1, 2);
    const float inv0 = 1.0f / rs0;
    const float inv1 = 1.0f / rs1;

    const int row0 = q0 + 16 * w + (lane >> 2);
    float* u0 = g_u + (((size_t)b * SEQ + row0) * NH + h) * HARM + (lane & 3) * 2;
    float* u1 = u0 + 8 * (size_t)NH * HARM;
#pragma unroll
    for (int nb = 0; nb < 4; nb++) {
        *reinterpret_cast<float2*>(u0 + nb * 16) =
            make_float2(U[2 * nb][0] * inv0, U[2 * nb][1] * inv0);
        *reinterpret_cast<float2*>(u1 + nb * 16) =
            make_float2(U[2 * nb][2] * inv1, U[2 * nb][3] * inv1);
        *reinterpret_cast<float2*>(u0 + nb * 16 + 8) =
            make_float2(U[2 * nb + 1][0] * inv0, U[2 * nb + 1][1] * inv0);
        *reinterpret_cast<float2*>(u1 + nb * 16 + 8) =
            make_float2(U[2 * nb + 1][2] * inv1, U[2 * nb + 1][3] * inv1);
    }
}

// ---------------- launch 5: wo = amp_o * cos(phase_o) --------------------------
__global__ __launch_bounds__(256)
void wo_kernel(const float* __restrict__ po, const float* __restrict__ ao) {
    int idx = blockIdx.x * 256 + threadIdx.x;
    if (idx < HID * HARM) g_wo[idx] = ao[idx] * cosf(po[idx]);
}

// ---------------- launch 6: res_o partials, split-K x4 -------------------------
__global__ __launch_bounds__(256)
void uproj_kernel() {
    __shared__ float As[16][68];
    __shared__ float Bs[16][68];
    const int tx = threadIdx.x, ty = threadIdx.y;
    const int tid = ty * 16 + tx;
    const int m0 = blockIdx.y * 64;
    const int kc = blockIdx.x;
    const int kbase = kc * 256;
    float acc[4][4] = {};
    for (int k0 = 0; k0 < 256; k0 += 16) {
#pragma unroll
        for (int i = 0; i < 4; i++) {
            int e = tid + i * 256;
            int r = e >> 4, kk = e & 15;
            As[kk][r] = g_u[(size_t)(m0 + r) * (NH * HARM) + kbase + k0 + kk];
            Bs[kk][r] = g_C[(size_t)r * (NH * HARM) + kbase + k0 + kk];
        }
        __syncthreads();
#pragma unroll
        for (int kk = 0; kk < 16; kk++) {
            float4 a4 = *reinterpret_cast<const float4*>(&As[kk][ty * 4]);
            float4 b4 = *reinterpret_cast<const float4*>(&Bs[kk][tx * 4]);
            float av[4] = {a4.x, a4.y, a4.z, a4.w};
            float bv[4] = {b4.x, b4.y, b4.z, b4.w};
#pragma unroll
            for (int i = 0; i < 4; i++)
#pragma unroll
                for (int j = 0; j < 4; j++)
                    acc[i][j] += av[i] * bv[j];
        }
        __syncthreads();
    }
    float* out = g_reso4 + (size_t)kc * MTOT * HARM;
#pragma unroll
    for (int i = 0; i < 4; i++) {
        int m = m0 + ty * 4 + i;
#pragma unroll
        for (int j = 0; j < 4; j++)
            out[(size_t)m * HARM + tx * 4 + j] = acc[i][j];
    }
}

// ---------------- launch 7: out = (sum of partials) @ Wo^T ---------------------
__global__ __launch_bounds__(256)
void out_kernel(float* __restrict__ C) {
    __shared__ float As[16][68];
    __shared__ float Bs[16][68];
    const int tx = threadIdx.x, ty = threadIdx.y;
    const int tid = ty * 16 + tx;
    const int m0 = blockIdx.y * 64, n0 = blockIdx.x * 64;
    float acc[4][4] = {};
    for (int k0 = 0; k0 < HARM; k0 += 16) {
#pragma unroll
        for (int i = 0; i < 4; i++) {
            int e = tid + i * 256;
            int r = e >> 4, kk = e & 15;
            size_t o = (size_t)(m0 + r) * HARM + k0 + kk;
            As[kk][r] = g_reso4[o] + g_reso4[o + (size_t)MTOT * HARM]
                      + g_reso4[o + 2 * (size_t)MTOT * HARM]
                      + g_reso4[o + 3 * (size_t)MTOT * HARM];
            Bs[kk][r] = g_wo[(size_t)(n0 + r) * HARM + k0 + kk];
        }
        __syncthreads();
#pragma unroll
        for (int kk = 0; kk < 16; kk++) {
            float4 a4 = *reinterpret_cast<const float4*>(&As[kk][ty * 4]);
            float4 b4 = *reinterpret_cast<const float4*>(&Bs[kk][tx * 4]);
            float av[4] = {a4.x, a4.y, a4.z, a4.w};
            float bv[4] = {b4.x, b4.y, b4.z, b4.w};
#pragma unroll
            for (int i = 0; i < 4; i++)
#pragma unroll
                for (int j = 0; j < 4; j++)
                    acc[i][j] += av[i] * bv[j];
        }
        __syncthreads();
    }
#pragma unroll
    for (int i = 0; i < 4; i++) {
        int m = m0 + ty * 4 + i;
#pragma unroll
        for (int j = 0; j < 4; j++)
            C[(size_t)m * HID + n0 + tx * 4 + j] = acc[i][j];
    }
}

// ---------------- launcher ----------------------------------------------------
extern "C" void kernel_launch(void* const* d_in, const int* in_sizes, int n_in,
                              void* d_out, int out_size) {
    const float* x  = (const float*)d_in[0];
    const float* bq = (const float*)d_in[1];
    const float* pq = (const float*)d_in[2];
    const float* aq = (const float*)d_in[3];
    const float* bk = (const float*)d_in[4];
    const float* pk = (const float*)d_in[5];
    const float* ak = (const float*)d_in[6];
    const float* bv = (const float*)d_in[7];
    const float* pv = (const float*)d_in[8];
    const float* av = (const float*)d_in[9];
    const float* bo = (const float*)d_in[10];
    const float* po = (const float*)d_in[11];
    const float* ao = (const float*)d_in[12];
    float* out = (float*)d_out;

    dim3 thr(16, 16);
    // 1: per-head G and C (w computed inline)
    gc_kernel<<<32, thr>>>(pq, aq, pk, ak, pv, av, bo);
    // 2: resonances; rq fp32, rk/rv bf16 hi/lo (rv transposed)
    res_kernel<<<dim3(3, MTOT / 64), thr>>>(x, bq, bk, bv);
    // 3: T = K2 * Res_q G^T -> bf16 hi/lo
    tproj_kernel<<<dim3(NH * HARM / 64, MTOT / 64), thr>>>();

    // 4: attention  (profiled slot)
    cudaFuncSetAttribute(flash_mma_kernel,
                         cudaFuncAttributeMaxDynamicSharedMemorySize, FA_SMEM);
    flash_mma_kernel<<<dim3(SEQ / BQ, BATCH * NH), 256, FA_SMEM>>>();

    // 5: wo weights
    wo_kernel<<<(HID * HARM + 255) / 256, 256>>>(po, ao);
    // 6: res_o partials (split-K x4)
    uproj_kernel<<<dim3(4, MTOT / 64), thr>>>();
    // 7: out = res_o @ Wo^T
    out_kernel<<<dim3(HID / 64, MTOT / 64), thr>>>(out);
}